// round 15
// baseline (speedup 1.0000x reference)
#include <cuda_runtime.h>

// Problem constants
#define Bn     32
#define Cn     40
#define Ln     16000
#define Kn     128
#define Sn     125      // LS / STRIDE
#define STILE  32       // s-values per block
#define NTILES 4        // ceil(125/32)
#define NOUT   (Bn * Cn * Sn)   // 160000 outputs (real part)

// ---- packed f32x2 helpers (Blackwell sm_103a) ----
#define FMA2(acc, a, b) \
    asm("fma.rn.f32x2 %0, %1, %2, %0;" : "+l"(acc) : "l"(a), "l"(b))
#define UNPACK2(lo, hi, in) \
    asm("mov.b64 {%0, %1}, %2;" : "=f"(lo), "=f"(hi) : "l"(in))

// ---------------- fast mode-0 kernel (real part only) ----------------
// Grid (4, 32), 1024 threads = 32 warps (R10's proven shape).
//   warp w: g8 = w&7 -> channel group (5 channels), q = w>>3 -> 32-tap slice
//   lane   = s within the 32-s tile
// Key trick vs R10: x tile stored TAP-REVERSED in smem:
//   xs[sl][m] = x[(128*(s0+sl) - m) mod L],  m = tap index 0..127
// so y[s] = sum_m h[m]*xs[sl][m] is a straight aligned dot product and
// consecutive taps form natural 16B pairs on BOTH sides -> fma.rn.f32x2
// with zero register packing and zero kernel repacking. acc.lo/.hi hold
// even/odd tap sums; folded once before the partial store.
// Kernel loads remain warp-uniform (broadcast, 1 wavefront each).
//
// smem (floats):
//   ks   : plain copy of kr, 5120            (20480 B)
//   xs   : 32 segments x 132 (pad)           (16896 B)
//   part : 4 slices x 40 ch x 32 lanes       (20480 B)
#define KS_FLOATS   (Cn * Kn)          // 5120
#define XSEG        132
#define XS_FLOATS   (32 * XSEG)        // 4224
#define PART_FLOATS (4 * Cn * 32)      // 5120
#define SMEMB_FAST  ((KS_FLOATS + XS_FLOATS + PART_FLOATS) * 4)   // 57856 B

__global__ __launch_bounds__(1024, 1)
void isac_conv_fast(const float* __restrict__ x,
                    const float* __restrict__ kr,
                    float* __restrict__ out)
{
    extern __shared__ float sm[];
    float* ks   = sm;
    float* xs   = sm + KS_FLOATS;
    float* part = sm + KS_FLOATS + XS_FLOATS;

    const int tid   = threadIdx.x;
    const int stile = blockIdx.x;
    const int b     = blockIdx.y;

    // ---- kernel stage: straight float4 copy (no reversal needed) ----
    #pragma unroll
    for (int idx = tid; idx < KS_FLOATS / 4; idx += 1024)
        ((float4*)ks)[idx] = ((const float4*)kr)[idx];

    // ---- x tile, tap-reversed: xs[sl][m] = x[(128*(s0+sl) - m) mod L] ----
    const int base = stile * (STILE * Kn);   // 128*s0
    const float* xb = x + b * Ln;
    #pragma unroll
    for (int i = 0; i < 4; i++) {
        const int j  = tid + i * 1024;       // j < 4096
        const int sl = j >> 7, m = j & 127;
        int g = base + sl * Kn - m;
        if (g < 0)        g += Ln;
        else if (g >= Ln) g -= Ln;
        xs[sl * XSEG + m] = xb[g];
    }
    __syncthreads();

    // ---- compute: 5 channels x 32-tap slice per thread ----
    const int lane = tid & 31;               // s within tile
    const int w    = tid >> 5;
    const int g8   = w & 7;                  // channel group
    const int q    = w >> 3;                 // 32-tap K slice
    const int c0   = g8 * 5;

    // ull2 units (16B = 4 taps): xs lane offset = (lane*132)*4 B (16B-mult),
    // q offset = 32 taps = 128B. ks channel stride = 128 taps = 32 ull2.
    const ulonglong2* xp = (const ulonglong2*)(xs + lane * XSEG + q * 32);
    const ulonglong2* kp = (const ulonglong2*)ks + (c0 * 32 + q * 8);

    unsigned long long acc[5] = {0ull, 0ull, 0ull, 0ull, 0ull};

    #pragma unroll
    for (int i = 0; i < 8; i++) {            // 4 taps per iter
        const ulonglong2 xv = xp[i];         // ((x[t],x[t+1]),(x[t+2],x[t+3]))
        #pragma unroll
        for (int j = 0; j < 5; j++) {
            const ulonglong2 kv = kp[j * 32 + i];   // broadcast
            FMA2(acc[j], xv.x, kv.x);
            FMA2(acc[j], xv.y, kv.y);
        }
    }

    // ---- fold even/odd tap sums, store scalar partials ----
    #pragma unroll
    for (int j = 0; j < 5; j++) {
        float lo, hi;
        UNPACK2(lo, hi, acc[j]);
        part[q * (Cn * 32) + (c0 + j) * 32 + lane] = lo + hi;
    }
    __syncthreads();

    // ---- reduce 4 K-slices, write (B, C, 125) float32 ----
    const int s0 = stile * STILE;
    #pragma unroll
    for (int idx = tid; idx < Cn * 32; idx += 1024) {
        const int c = idx >> 5, s = idx & 31;
        const float v = part[idx]
                      + part[1 * Cn * 32 + idx]
                      + part[2 * Cn * 32 + idx]
                      + part[3 * Cn * 32 + idx];
        if (s0 + s < Sn)
            out[(b * Cn + c) * Sn + (s0 + s)] = v;
    }
}

// ---------------- fallback (full complex) — not expected to trigger ----------------
#define KERN_FLOATS (Cn * Kn)
#define SMEMB_FB ((2 * KERN_FLOATS + 32 * XSEG) * 4)

__global__ __launch_bounds__(256)
void isac_conv_fallback(const float* __restrict__ x,
                        const float* __restrict__ kr,
                        const float* __restrict__ ki,
                        float* __restrict__ out,
                        int mode)   // 1 = planar, 2 = interleaved
{
    extern __shared__ float smem[];
    float* kr_s = smem;
    float* ki_s = smem + KERN_FLOATS;
    float* xs   = smem + 2 * KERN_FLOATS;

    const int tid = threadIdx.x, stile = blockIdx.x, b = blockIdx.y;
    #pragma unroll 4
    for (int idx = tid; idx < KERN_FLOATS; idx += 256) {
        const int c = idx >> 7, m = idx & 127;
        kr_s[idx] = kr[c * Kn + (127 - m)];
        ki_s[idx] = ki[c * Kn + (127 - m)];
    }
    const int gstart = stile * (STILE * Kn) - 127;
    const float* xb = x + b * Ln;
    #pragma unroll 4
    for (int j = tid; j < 32 * Kn; j += 256) {
        int g = gstart + j;
        if (g < 0) g += Ln; else if (g >= Ln) g -= Ln;
        xs[(j >> 7) * XSEG + (j & 127)] = xb[g];
    }
    __syncthreads();

    const int lane = tid & 31, w = tid >> 5;
    const int s = stile * STILE + lane, c0 = w * 5;
    const float4* xp  = (const float4*)(xs + lane * XSEG);
    const float4* krp = (const float4*)(kr_s + c0 * Kn);
    const float4* kip = (const float4*)(ki_s + c0 * Kn);

    float ar[5] = {0,0,0,0,0}, ai[5] = {0,0,0,0,0};
    #pragma unroll 2
    for (int m4 = 0; m4 < Kn / 4; m4++) {
        const float4 xv = xp[m4];
        #pragma unroll
        for (int cc = 0; cc < 5; cc++) {
            const float4 kv = krp[cc * (Kn / 4) + m4];
            const float4 iv = kip[cc * (Kn / 4) + m4];
            ar[cc] = fmaf(xv.x, kv.x, fmaf(xv.y, kv.y, fmaf(xv.z, kv.z, fmaf(xv.w, kv.w, ar[cc]))));
            ai[cc] = fmaf(xv.x, iv.x, fmaf(xv.y, iv.y, fmaf(xv.z, iv.z, fmaf(xv.w, iv.w, ai[cc]))));
        }
    }
    if (s < Sn) {
        if (mode == 1) {
            #pragma unroll
            for (int cc = 0; cc < 5; cc++) {
                const int idx = (b * Cn + (c0 + cc)) * Sn + s;
                out[idx] = ar[cc]; out[NOUT + idx] = ai[cc];
            }
        } else {
            float2* o2 = (float2*)out;
            #pragma unroll
            for (int cc = 0; cc < 5; cc++)
                o2[(b * Cn + (c0 + cc)) * Sn + s] = make_float2(ar[cc], ai[cc]);
        }
    }
}

extern "C" void kernel_launch(void* const* d_in, const int* in_sizes, int n_in,
                              void* d_out, int out_size)
{
    const float* x  = (const float*)d_in[0];   // (32, 1, 16000) f32
    const float* kr = (const float*)d_in[1];   // (40, 128) f32
    const float* ki = (const float*)d_in[2];   // (40, 128) f32
    float* out = (float*)d_out;

    if (out_size == NOUT) {
        cudaFuncSetAttribute(isac_conv_fast,
                             cudaFuncAttributeMaxDynamicSharedMemorySize, SMEMB_FAST);
        dim3 grid(NTILES, Bn);
        isac_conv_fast<<<grid, 1024, SMEMB_FAST>>>(x, kr, out);
    } else {
        const int mode = (out_size == 2 * NOUT) ? 1 : 2;
        cudaFuncSetAttribute(isac_conv_fallback,
                             cudaFuncAttributeMaxDynamicSharedMemorySize, SMEMB_FB);
        dim3 grid(NTILES, Bn);
        isac_conv_fallback<<<grid, 256, SMEMB_FB>>>(x, kr, ki, out, mode);
    }
}

// round 16
// speedup vs baseline: 1.1674x; 1.1674x over previous
#include <cuda_runtime.h>

// Problem constants
#define Bn     32
#define Cn     40
#define Ln     16000
#define Kn     128
#define Sn     125      // LS / STRIDE
#define STILE  16       // s-values per block
#define NTILES 8        // 8*16 = 128 >= 125
#define NOUT   (Bn * Cn * Sn)   // 160000 outputs (real part)

// ---- packed f32x2 helpers (Blackwell sm_103a) ----
#define FMA2(acc, a, b) \
    asm("fma.rn.f32x2 %0, %1, %2, %0;" : "+l"(acc) : "l"(a), "l"(b))
#define UNPACK2(lo, hi, in) \
    asm("mov.b64 {%0, %1}, %2;" : "=f"(lo), "=f"(hi) : "l"(in))

// ---------------- fast mode-0 kernel (real part only) ----------------
// Grid (8, 32) = 256 blocks x 512 threads, __launch_bounds__(512, 2):
// 2 CTAs co-resident per SM (32KB regs, 38.9KB smem each) -> one CTA's
// prologue/barrier/drain overlaps the other's mainloop; single wave.
//
//   warp w (16): g4 = w&3 -> 10-channel group, q = w>>2 -> 32-tap K slice
//   lane:        sl = lane&15 -> s within tile, dd = lane>>4 -> 5-ch half
//   thread: 5 channels (c0 = g4*10 + dd*5) x 32 taps, FMA2 over tap pairs.
//
// x tile stored TAP-REVERSED: xs[sl][m] = x[(128*(s0+sl) - m) mod L], so the
// dot product is aligned on both sides (zero packing, zero kernel reversal).
// ks rows padded to 132 floats: dd=0/1 kernel addresses differ by 5*132
// floats (bank 20 apart) -> both served in one wavefront.
// K-slice reduction via part smem (4 slices), final 640-thread pass.
//
// smem (floats): ks 40*132=5280 | xs 16*132=2112 | part 4*40*16=2560
#define KSEG      132
#define XSEG      132
#define KS_FLOATS (Cn * KSEG)          // 5280
#define XS_FLOATS (STILE * XSEG)       // 2112
#define PART_FLOATS (4 * Cn * STILE)   // 2560
#define SMF_FAST  (KS_FLOATS + XS_FLOATS + PART_FLOATS)   // 9952 f = 39808 B

__global__ __launch_bounds__(512, 2)
void isac_conv_fast(const float* __restrict__ x,
                    const float* __restrict__ kr,
                    float* __restrict__ out)
{
    __shared__ float sm[SMF_FAST];
    float* ks   = sm;
    float* xs   = sm + KS_FLOATS;
    float* part = sm + KS_FLOATS + XS_FLOATS;

    const int tid   = threadIdx.x;
    const int stile = blockIdx.x;
    const int b     = blockIdx.y;

    // ---- kernel copy into padded rows: ks[c*132 + t] = kr[c*128 + t] ----
    #pragma unroll
    for (int i = 0; i < 10; i++) {
        const int idx = tid + i * 512;           // idx < 5120
        ks[(idx >> 7) * KSEG + (idx & 127)] = kr[idx];
    }

    // ---- x tile, tap-reversed: xs[sl][m] = x[(128*(s0+sl) - m) mod L] ----
    const int base = stile * (STILE * Kn);       // 128*s0
    const float* xb = x + b * Ln;
    #pragma unroll
    for (int i = 0; i < 4; i++) {
        const int j  = tid + i * 512;            // j < 2048
        const int sl = j >> 7, m = j & 127;
        int g = base + sl * Kn - m;
        if (g < 0)        g += Ln;
        else if (g >= Ln) g -= Ln;
        xs[sl * XSEG + m] = xb[g];
    }
    __syncthreads();

    // ---- compute: 5 channels x 32-tap slice per thread ----
    const int lane = tid & 31;
    const int w    = tid >> 5;
    const int g4   = w & 3;                      // 10-channel group
    const int q    = w >> 2;                     // 32-tap K slice
    const int sl   = lane & 15;                  // s within tile
    const int dd   = lane >> 4;                  // 5-channel half
    const int c0   = g4 * 10 + dd * 5;

    const ulonglong2* xp = (const ulonglong2*)(xs + sl * XSEG + q * 32);
    const float* kbase = ks + c0 * KSEG + q * 32;

    unsigned long long acc[5] = {0ull, 0ull, 0ull, 0ull, 0ull};

    #pragma unroll
    for (int i = 0; i < 8; i++) {                // 4 taps per iter
        const ulonglong2 xv = xp[i];             // ((x[t],x[t+1]),(x[t+2],x[t+3]))
        #pragma unroll
        for (int j = 0; j < 5; j++) {
            const ulonglong2 kv =
                ((const ulonglong2*)(kbase + j * KSEG))[i];   // 2 addrs/warp
            FMA2(acc[j], xv.x, kv.x);
            FMA2(acc[j], xv.y, kv.y);
        }
    }

    // ---- fold even/odd tap sums, store scalar partials ----
    #pragma unroll
    for (int j = 0; j < 5; j++) {
        float lo, hi;
        UNPACK2(lo, hi, acc[j]);
        part[q * (Cn * STILE) + (c0 + j) * STILE + sl] = lo + hi;
    }
    __syncthreads();

    // ---- reduce 4 K-slices, write (B, C, 125) float32 ----
    const int s0 = stile * STILE;
    #pragma unroll
    for (int idx = tid; idx < Cn * STILE; idx += 512) {
        const int c = idx >> 4, s = idx & 15;
        const float v = part[idx]
                      + part[1 * Cn * STILE + idx]
                      + part[2 * Cn * STILE + idx]
                      + part[3 * Cn * STILE + idx];
        if (s0 + s < Sn)
            out[(b * Cn + c) * Sn + (s0 + s)] = v;
    }
}

// ---------------- fallback (full complex) — not expected to trigger ----------------
#define KERN_FLOATS (Cn * Kn)
#define FXSEG 132
#define SMEMB_FB ((2 * KERN_FLOATS + 32 * FXSEG) * 4)

__global__ __launch_bounds__(256)
void isac_conv_fallback(const float* __restrict__ x,
                        const float* __restrict__ kr,
                        const float* __restrict__ ki,
                        float* __restrict__ out,
                        int mode)   // 1 = planar, 2 = interleaved
{
    extern __shared__ float smem[];
    float* kr_s = smem;
    float* ki_s = smem + KERN_FLOATS;
    float* xs   = smem + 2 * KERN_FLOATS;

    const int tid = threadIdx.x, stile = blockIdx.x, b = blockIdx.y;
    #pragma unroll 4
    for (int idx = tid; idx < KERN_FLOATS; idx += 256) {
        const int c = idx >> 7, m = idx & 127;
        kr_s[idx] = kr[c * Kn + (127 - m)];
        ki_s[idx] = ki[c * Kn + (127 - m)];
    }
    const int gstart = stile * (32 * Kn) - 127;
    const float* xb = x + b * Ln;
    #pragma unroll 4
    for (int j = tid; j < 32 * Kn; j += 256) {
        int g = gstart + j;
        if (g < 0) g += Ln; else if (g >= Ln) g -= Ln;
        xs[(j >> 7) * FXSEG + (j & 127)] = xb[g];
    }
    __syncthreads();

    const int lane = tid & 31, w = tid >> 5;
    const int s = stile * 32 + lane, c0 = w * 5;
    const float4* xp  = (const float4*)(xs + lane * FXSEG);
    const float4* krp = (const float4*)(kr_s + c0 * Kn);
    const float4* kip = (const float4*)(ki_s + c0 * Kn);

    float ar[5] = {0,0,0,0,0}, ai[5] = {0,0,0,0,0};
    #pragma unroll 2
    for (int m4 = 0; m4 < Kn / 4; m4++) {
        const float4 xv = xp[m4];
        #pragma unroll
        for (int cc = 0; cc < 5; cc++) {
            const float4 kv = krp[cc * (Kn / 4) + m4];
            const float4 iv = kip[cc * (Kn / 4) + m4];
            ar[cc] = fmaf(xv.x, kv.x, fmaf(xv.y, kv.y, fmaf(xv.z, kv.z, fmaf(xv.w, kv.w, ar[cc]))));
            ai[cc] = fmaf(xv.x, iv.x, fmaf(xv.y, iv.y, fmaf(xv.z, iv.z, fmaf(xv.w, iv.w, ai[cc]))));
        }
    }
    if (s < Sn) {
        if (mode == 1) {
            #pragma unroll
            for (int cc = 0; cc < 5; cc++) {
                const int idx = (b * Cn + (c0 + cc)) * Sn + s;
                out[idx] = ar[cc]; out[NOUT + idx] = ai[cc];
            }
        } else {
            float2* o2 = (float2*)out;
            #pragma unroll
            for (int cc = 0; cc < 5; cc++)
                o2[(b * Cn + (c0 + cc)) * Sn + s] = make_float2(ar[cc], ai[cc]);
        }
    }
}

extern "C" void kernel_launch(void* const* d_in, const int* in_sizes, int n_in,
                              void* d_out, int out_size)
{
    const float* x  = (const float*)d_in[0];   // (32, 1, 16000) f32
    const float* kr = (const float*)d_in[1];   // (40, 128) f32
    const float* ki = (const float*)d_in[2];   // (40, 128) f32
    float* out = (float*)d_out;

    if (out_size == NOUT) {
        dim3 grid(NTILES, Bn);
        isac_conv_fast<<<grid, 512>>>(x, kr, out);
    } else {
        const int mode = (out_size == 2 * NOUT) ? 1 : 2;
        cudaFuncSetAttribute(isac_conv_fallback,
                             cudaFuncAttributeMaxDynamicSharedMemorySize, SMEMB_FB);
        dim3 grid(4, Bn);
        isac_conv_fallback<<<grid, 256, SMEMB_FB>>>(x, kr, ki, out, mode);
    }
}